// round 1
// baseline (speedup 1.0000x reference)
#include <cuda_runtime.h>
#include <cuda_bf16.h>
#include <float.h>
#include <stdint.h>

// Problem constants
#define N_BUG  200000
#define N_USER 100000
#define NEDGE  2000000
#define IN_DIM 256
#define HID    128
#define OUT_CH 64
#define NCLS   128

#define CEILDIV(a,b) (((a)+(b)-1)/(b))

// ---------------------------------------------------------------------------
// Device scratch (static allocation; no cudaMalloc allowed)
// ---------------------------------------------------------------------------
__device__ float g_hb1[(size_t)N_BUG  * HID];     // layer1 bug projections
__device__ float g_hu1[(size_t)N_USER * HID];     // layer1 user projections
__device__ float g_zu [(size_t)N_USER * HID];     // z_user (post-relu)
__device__ float g_zb [(size_t)N_BUG  * HID];     // z_bug  (post-relu)
__device__ float g_hb2[(size_t)N_BUG  * OUT_CH];
__device__ float g_hu2[(size_t)N_USER * OUT_CH];
__device__ float g_z2 [(size_t)N_BUG  * OUT_CH];

__device__ float g_sb_s[N_BUG * 2];    // hb1 . a1_bu_s  (bug as src in bu)
__device__ float g_sb_d[N_BUG * 2];    // hb1 . a1_ub_d  (bug as dst in ub)
__device__ float g_su_s[N_USER * 2];   // hu1 . a1_ub_s
__device__ float g_su_d[N_USER * 2];   // hu1 . a1_bu_d
__device__ float g_sb2[N_BUG];         // hb2 . a2_ub_d
__device__ float g_su2[N_USER];        // hu2 . a2_ub_s

__device__ int g_deg[N_BUG];           // reused histogram
__device__ int g_cursor[N_BUG];        // reused fill cursor
__device__ int g_off_u[N_USER + 1];    // CSR by user-dst (ebu edges)
__device__ int g_off_b[N_BUG + 1];     // CSR by bug-dst  (eub edges)
__device__ int g_csrc_bu[NEDGE];       // src (bug) ids in CSR order
__device__ int g_csrc_ub[NEDGE];       // src (user) ids in CSR order

// ---------------------------------------------------------------------------
// CSR build
// ---------------------------------------------------------------------------
__global__ void zero_int_kernel(int* __restrict__ p, int n) {
    int i = blockIdx.x * blockDim.x + threadIdx.x;
    if (i < n) p[i] = 0;
}

__global__ void count_deg_kernel(const int* __restrict__ dst, int* __restrict__ deg, int E) {
    int e = blockIdx.x * blockDim.x + threadIdx.x;
    if (e < E) atomicAdd(&deg[dst[e]], 1);
}

// single-block exclusive scan (n up to 200k); writes off[0..n] and cursor[0..n-1]
__global__ void exscan_kernel(const int* __restrict__ deg, int* __restrict__ off,
                              int* __restrict__ cursor, int n) {
    __shared__ int s_warp[32];
    __shared__ int s_carry;
    int tid = threadIdx.x;              // 1024 threads
    int lane = tid & 31, wid = tid >> 5;
    if (tid == 0) s_carry = 0;
    __syncthreads();
    for (int base = 0; base < n; base += 1024) {
        int i = base + tid;
        int v = (i < n) ? deg[i] : 0;
        int inc = v;
        #pragma unroll
        for (int o = 1; o < 32; o <<= 1) {
            int t = __shfl_up_sync(0xffffffffu, inc, o);
            if (lane >= o) inc += t;
        }
        if (lane == 31) s_warp[wid] = inc;
        __syncthreads();
        if (wid == 0) {
            int wv = s_warp[lane];
            int winc = wv;
            #pragma unroll
            for (int o = 1; o < 32; o <<= 1) {
                int t = __shfl_up_sync(0xffffffffu, winc, o);
                if (lane >= o) winc += t;
            }
            s_warp[lane] = winc - wv;   // exclusive warp offset
        }
        __syncthreads();
        int excl = s_carry + s_warp[wid] + inc - v;
        if (i < n) { off[i] = excl; cursor[i] = excl; }
        __syncthreads();
        if (tid == 1023) s_carry = excl + v;
        __syncthreads();
    }
    if (threadIdx.x == 0) off[n] = s_carry;
}

__global__ void fill_csr_kernel(const int* __restrict__ src, const int* __restrict__ dst,
                                int* __restrict__ cursor, int* __restrict__ csrc, int E) {
    int e = blockIdx.x * blockDim.x + threadIdx.x;
    if (e >= E) return;
    int d = dst[e];
    int pos = atomicAdd(&cursor[d], 1);
    csrc[pos] = src[e];
}

// ---------------------------------------------------------------------------
// GEMM: C[N,M] = A[N,K] @ W[K,M] + bias  (fp32, packed f32x2 FMA)
// BM=128, BN=64, BK=16, 256 threads, each thread 8x4 outputs.
// ---------------------------------------------------------------------------
#define GBM 128
#define GBN 64
#define GBK 16

__global__ __launch_bounds__(256) void gemm_bias_kernel(
    const float* __restrict__ A, const float* __restrict__ W,
    const float* __restrict__ bias, float* __restrict__ C,
    int N, int K, int M) {
    __shared__ float As[GBK][GBM];     // transposed A tile
    __shared__ float Ws[GBK][GBN];
    int tid = threadIdx.x;
    int tx = tid & 15;                 // 0..15 -> output col group (4 cols)
    int ty = tid >> 4;                 // 0..15 -> output row group (8 rows)
    int rowBase = blockIdx.y * GBM;
    int colBase = blockIdx.x * GBN;

    unsigned long long acc01[8], acc23[8];
    #pragma unroll
    for (int i = 0; i < 8; i++) { acc01[i] = 0ull; acc23[i] = 0ull; }

    for (int k0 = 0; k0 < K; k0 += GBK) {
        // A tile: 128x16 = 512 float4, 2 per thread
        #pragma unroll
        for (int t = 0; t < 2; t++) {
            int idx = tid + t * 256;
            int r  = idx >> 2;
            int c4 = idx & 3;
            float4 v = make_float4(0.f, 0.f, 0.f, 0.f);
            int gr = rowBase + r;
            if (gr < N)
                v = *(const float4*)(A + (size_t)gr * K + k0 + c4 * 4);
            As[c4*4+0][r] = v.x; As[c4*4+1][r] = v.y;
            As[c4*4+2][r] = v.z; As[c4*4+3][r] = v.w;
        }
        // W tile: 16x64 = 256 float4, 1 per thread
        {
            int kk = tid >> 4;
            int c4 = tid & 15;
            float4 v = *(const float4*)(W + (size_t)(k0 + kk) * M + colBase + c4 * 4);
            *(float4*)&Ws[kk][c4 * 4] = v;
        }
        __syncthreads();
        #pragma unroll
        for (int k = 0; k < GBK; k++) {
            float4 a0 = *(const float4*)&As[k][ty * 8];
            float4 a1 = *(const float4*)&As[k][ty * 8 + 4];
            float4 b  = *(const float4*)&Ws[k][tx * 4];
            unsigned long long b01, b23;
            asm("mov.b64 %0, {%1, %2};" : "=l"(b01) : "f"(b.x), "f"(b.y));
            asm("mov.b64 %0, {%1, %2};" : "=l"(b23) : "f"(b.z), "f"(b.w));
            float av[8] = {a0.x, a0.y, a0.z, a0.w, a1.x, a1.y, a1.z, a1.w};
            #pragma unroll
            for (int i = 0; i < 8; i++) {
                unsigned long long ai;
                asm("mov.b64 %0, {%1, %1};" : "=l"(ai) : "f"(av[i]));
                asm("fma.rn.f32x2 %0, %1, %2, %0;" : "+l"(acc01[i]) : "l"(ai), "l"(b01));
                asm("fma.rn.f32x2 %0, %1, %2, %0;" : "+l"(acc23[i]) : "l"(ai), "l"(b23));
            }
        }
        __syncthreads();
    }
    float4 bb = *(const float4*)(bias + colBase + tx * 4);
    #pragma unroll
    for (int i = 0; i < 8; i++) {
        int gr = rowBase + ty * 8 + i;
        if (gr < N) {
            float o0, o1, o2, o3;
            asm("mov.b64 {%0, %1}, %2;" : "=f"(o0), "=f"(o1) : "l"(acc01[i]));
            asm("mov.b64 {%0, %1}, %2;" : "=f"(o2), "=f"(o3) : "l"(acc23[i]));
            float4 o = make_float4(o0 + bb.x, o1 + bb.y, o2 + bb.z, o3 + bb.w);
            *(float4*)(C + (size_t)gr * M + colBase + tx * 4) = o;
        }
    }
}

// ---------------------------------------------------------------------------
// Per-node attention scores
// ---------------------------------------------------------------------------
// H=2, C=128: compute two score pairs per node (two att matrices at once)
__global__ __launch_bounds__(256) void node_scores2_kernel(
    const float* __restrict__ X, const float* __restrict__ attA,
    const float* __restrict__ attB, float* __restrict__ sA,
    float* __restrict__ sB, int N) {
    int w = (blockIdx.x * blockDim.x + threadIdx.x) >> 5;
    if (w >= N) return;
    int lane = threadIdx.x & 31;
    const float* xr = X + (size_t)w * 128;
    float x0 = xr[lane], x1 = xr[32 + lane], x2 = xr[64 + lane], x3 = xr[96 + lane];
    float a0 = x0 * attA[lane]      + x1 * attA[32 + lane];
    float a1 = x2 * attA[64 + lane] + x3 * attA[96 + lane];
    float b0 = x0 * attB[lane]      + x1 * attB[32 + lane];
    float b1 = x2 * attB[64 + lane] + x3 * attB[96 + lane];
    #pragma unroll
    for (int o = 16; o; o >>= 1) {
        a0 += __shfl_xor_sync(0xffffffffu, a0, o);
        a1 += __shfl_xor_sync(0xffffffffu, a1, o);
        b0 += __shfl_xor_sync(0xffffffffu, b0, o);
        b1 += __shfl_xor_sync(0xffffffffu, b1, o);
    }
    if (lane == 0) {
        sA[w * 2] = a0; sA[w * 2 + 1] = a1;
        sB[w * 2] = b0; sB[w * 2 + 1] = b1;
    }
}

// H=1, C=64: single score per node
__global__ __launch_bounds__(256) void node_scores1_kernel(
    const float* __restrict__ X, const float* __restrict__ att,
    float* __restrict__ sOut, int N) {
    int w = (blockIdx.x * blockDim.x + threadIdx.x) >> 5;
    if (w >= N) return;
    int lane = threadIdx.x & 31;
    const float* xr = X + (size_t)w * 64;
    float a = xr[lane] * att[lane] + xr[32 + lane] * att[32 + lane];
    #pragma unroll
    for (int o = 16; o; o >>= 1) a += __shfl_xor_sync(0xffffffffu, a, o);
    if (lane == 0) sOut[w] = a;
}

// ---------------------------------------------------------------------------
// Fused edge softmax + aggregation (online softmax, warp per dst node)
// out[d,:] = relu( sum_e exp(a_e) * x[src_e,:] / max(sum_e exp(a_e), 1e-16) )
// ---------------------------------------------------------------------------
__global__ __launch_bounds__(256) void attn_agg_h2c128_kernel(
    const int* __restrict__ off, const int* __restrict__ csrc,
    const float* __restrict__ ssrc, const float* __restrict__ sdst,
    const float* __restrict__ X, float* __restrict__ OUT, int Ndst) {
    int w = (blockIdx.x * blockDim.x + threadIdx.x) >> 5;
    if (w >= Ndst) return;
    int lane = threadIdx.x & 31;
    int head = lane >> 4;              // channels lane*4..lane*4+3 all in this head
    float sd = sdst[(size_t)w * 2 + head];
    int lo = off[w], hi = off[w + 1];
    float m = -3.0e38f, z = 0.f;
    float4 acc = make_float4(0.f, 0.f, 0.f, 0.f);
    for (int p = lo; p < hi; ++p) {
        int s = csrc[p];
        float a = ssrc[(size_t)s * 2 + head] + sd;
        a = (a > 0.f) ? a : 0.2f * a;                // leaky_relu 0.2
        float mn = fmaxf(m, a);
        float scale = expf(m - mn);
        float e = expf(a - mn);
        z = z * scale + e;
        m = mn;
        float4 x = *(const float4*)(X + (size_t)s * 128 + lane * 4);
        acc.x = acc.x * scale + e * x.x;
        acc.y = acc.y * scale + e * x.y;
        acc.z = acc.z * scale + e * x.z;
        acc.w = acc.w * scale + e * x.w;
    }
    float inv = 1.f / fmaxf(z, 1e-16f);
    float4 o;
    o.x = fmaxf(acc.x * inv, 0.f);
    o.y = fmaxf(acc.y * inv, 0.f);
    o.z = fmaxf(acc.z * inv, 0.f);
    o.w = fmaxf(acc.w * inv, 0.f);
    *(float4*)(OUT + (size_t)w * 128 + lane * 4) = o;
}

__global__ __launch_bounds__(256) void attn_agg_h1c64_kernel(
    const int* __restrict__ off, const int* __restrict__ csrc,
    const float* __restrict__ ssrc, const float* __restrict__ sdst,
    const float* __restrict__ X, float* __restrict__ OUT, int Ndst) {
    int w = (blockIdx.x * blockDim.x + threadIdx.x) >> 5;
    if (w >= Ndst) return;
    int lane = threadIdx.x & 31;
    float sd = sdst[w];
    int lo = off[w], hi = off[w + 1];
    float m = -3.0e38f, z = 0.f;
    float2 acc = make_float2(0.f, 0.f);
    for (int p = lo; p < hi; ++p) {
        int s = csrc[p];
        float a = ssrc[s] + sd;
        a = (a > 0.f) ? a : 0.2f * a;
        float mn = fmaxf(m, a);
        float scale = expf(m - mn);
        float e = expf(a - mn);
        z = z * scale + e;
        m = mn;
        float2 x = *(const float2*)(X + (size_t)s * 64 + lane * 2);
        acc.x = acc.x * scale + e * x.x;
        acc.y = acc.y * scale + e * x.y;
    }
    float inv = 1.f / fmaxf(z, 1e-16f);
    float2 o;
    o.x = fmaxf(acc.x * inv, 0.f);
    o.y = fmaxf(acc.y * inv, 0.f);
    *(float2*)(OUT + (size_t)w * 64 + lane * 2) = o;
}

// ---------------------------------------------------------------------------
// Host launch
// ---------------------------------------------------------------------------
static float* symf(const void* sym) { void* p = nullptr; cudaGetSymbolAddress(&p, sym); return (float*)p; }
static int*   symi(const void* sym) { void* p = nullptr; cudaGetSymbolAddress(&p, sym); return (int*)p; }

extern "C" void kernel_launch(void* const* d_in, const int* in_sizes, int n_in,
                              void* d_out, int out_size) {
    const float* xb      = (const float*)d_in[0];
    const float* xu      = (const float*)d_in[1];
    const int*   ebu_src = (const int*)d_in[2];
    const int*   ebu_dst = (const int*)d_in[3];
    const int*   eub_src = (const int*)d_in[4];
    const int*   eub_dst = (const int*)d_in[5];
    const float* w1_bug  = (const float*)d_in[6];
    const float* b1_bug  = (const float*)d_in[7];
    const float* w1_user = (const float*)d_in[8];
    const float* b1_user = (const float*)d_in[9];
    const float* a1_bu_s = (const float*)d_in[10];
    const float* a1_bu_d = (const float*)d_in[11];
    const float* a1_ub_s = (const float*)d_in[12];
    const float* a1_ub_d = (const float*)d_in[13];
    // d_in[14..16]: k1_w,k1_b,q1 -- dead (semantic attn over 1 relation = identity)
    const float* w2_bug  = (const float*)d_in[17];
    const float* b2_bug  = (const float*)d_in[18];
    const float* w2_user = (const float*)d_in[19];
    const float* b2_user = (const float*)d_in[20];
    // d_in[21..22]: a2_bu_* -- dead (layer-2 z_user unused)
    const float* a2_ub_s = (const float*)d_in[23];
    const float* a2_ub_d = (const float*)d_in[24];
    // d_in[25..27]: k2_w,k2_b,q2 -- dead
    const float* wc      = (const float*)d_in[28];
    const float* bc      = (const float*)d_in[29];
    float* out = (float*)d_out;

    float *hb1 = symf(g_hb1), *hu1 = symf(g_hu1);
    float *zu = symf(g_zu), *zb = symf(g_zb);
    float *hb2 = symf(g_hb2), *hu2 = symf(g_hu2), *z2 = symf(g_z2);
    float *sb_s = symf(g_sb_s), *sb_d = symf(g_sb_d);
    float *su_s = symf(g_su_s), *su_d = symf(g_su_d);
    float *sb2 = symf(g_sb2), *su2 = symf(g_su2);
    int *deg = symi(g_deg), *cursor = symi(g_cursor);
    int *off_u = symi(g_off_u), *off_b = symi(g_off_b);
    int *csrc_bu = symi(g_csrc_bu), *csrc_ub = symi(g_csrc_ub);

    const int TB = 256;
    const int EB = CEILDIV(NEDGE, TB);

    // --- CSR build: ebu (dst = user) ---
    zero_int_kernel<<<CEILDIV(N_USER, TB), TB>>>(deg, N_USER);
    count_deg_kernel<<<EB, TB>>>(ebu_dst, deg, NEDGE);
    exscan_kernel<<<1, 1024>>>(deg, off_u, cursor, N_USER);
    fill_csr_kernel<<<EB, TB>>>(ebu_src, ebu_dst, cursor, csrc_bu, NEDGE);
    // --- CSR build: eub (dst = bug) ---
    zero_int_kernel<<<CEILDIV(N_BUG, TB), TB>>>(deg, N_BUG);
    count_deg_kernel<<<EB, TB>>>(eub_dst, deg, NEDGE);
    exscan_kernel<<<1, 1024>>>(deg, off_b, cursor, N_BUG);
    fill_csr_kernel<<<EB, TB>>>(eub_src, eub_dst, cursor, csrc_ub, NEDGE);

    // --- Layer 1 projections ---
    {
        dim3 g(HID / GBN, CEILDIV(N_BUG, GBM));
        gemm_bias_kernel<<<g, 256>>>(xb, w1_bug, b1_bug, hb1, N_BUG, IN_DIM, HID);
    }
    {
        dim3 g(HID / GBN, CEILDIV(N_USER, GBM));
        gemm_bias_kernel<<<g, 256>>>(xu, w1_user, b1_user, hu1, N_USER, IN_DIM, HID);
    }

    // --- Layer 1 node scores (both roles per node set, one pass over h) ---
    node_scores2_kernel<<<CEILDIV(N_BUG, 8), 256>>>(hb1, a1_bu_s, a1_ub_d, sb_s, sb_d, N_BUG);
    node_scores2_kernel<<<CEILDIV(N_USER, 8), 256>>>(hu1, a1_ub_s, a1_bu_d, su_s, su_d, N_USER);

    // --- Layer 1 edge softmax + aggregation (relu fused; elu(relu(x))==relu(x)) ---
    attn_agg_h2c128_kernel<<<CEILDIV(N_USER, 8), 256>>>(off_u, csrc_bu, sb_s, su_d, hb1, zu, N_USER);
    attn_agg_h2c128_kernel<<<CEILDIV(N_BUG, 8), 256>>>(off_b, csrc_ub, su_s, sb_d, hu1, zb, N_BUG);

    // --- Layer 2 projections ---
    {
        dim3 g(OUT_CH / GBN, CEILDIV(N_BUG, GBM));
        gemm_bias_kernel<<<g, 256>>>(zb, w2_bug, b2_bug, hb2, N_BUG, HID, OUT_CH);
    }
    {
        dim3 g(OUT_CH / GBN, CEILDIV(N_USER, GBM));
        gemm_bias_kernel<<<g, 256>>>(zu, w2_user, b2_user, hu2, N_USER, HID, OUT_CH);
    }

    // --- Layer 2 scores + aggregation (only bug-dst relation is live) ---
    node_scores1_kernel<<<CEILDIV(N_BUG, 8), 256>>>(hb2, a2_ub_d, sb2, N_BUG);
    node_scores1_kernel<<<CEILDIV(N_USER, 8), 256>>>(hu2, a2_ub_s, su2, N_USER);
    attn_agg_h1c64_kernel<<<CEILDIV(N_BUG, 8), 256>>>(off_b, csrc_ub, su2, sb2, hu2, z2, N_BUG);

    // --- Classifier ---
    {
        dim3 g(NCLS / GBN, CEILDIV(N_BUG, GBM));
        gemm_bias_kernel<<<g, 256>>>(z2, wc, bc, out, N_BUG, OUT_CH, NCLS);
    }
}